// round 5
// baseline (speedup 1.0000x reference)
#include <cuda_runtime.h>
#include <cuda.h>
#include <cuda_fp16.h>
#include <cstdint>

// ============================================================================
// convDU: bidirectional recurrent conv along H.
//   step: y = relu(Wm @ carry + b) + x     (Wm = W[:,:,4,0], 2048x2048)
// 94 serial GEMM steps of [2048x2048]x[2048x384].
// tcgen05 is rejected by this toolchain (.target sm_103, no 'a' features), so
// use base-ISA tensor cores: TMA+mbarrier pipeline -> ldmatrix -> mma.sync
// m16n8k16 f16 with fp32 accumulators.
// ============================================================================

#define CDU_C   2048
#define CDU_NB  4
#define CDU_H   48
#define CDU_W   96
#define CDU_NW  (CDU_NB * CDU_W)     // 384
#define CDU_HW  (CDU_H * CDU_W)      // 4608

#define M_TILE  64
#define N_TILE  96                   // one image's w-columns per CTA
#define KC      64                   // k elems per stage (64 * 2B = 128B SW128 row)
#define KITERS  (CDU_C / KC)         // 32
#define STAGES  6

#define A_STAGE_BYTES (M_TILE * 128)     // 8192
#define B_STAGE_BYTES (N_TILE * 128)     // 12288
#define SMEM_BAR      64                 // full[s] @ 64+16s, empty[s] @ +8
#define SMEM_A        1024
#define SMEM_B        (SMEM_A + STAGES * A_STAGE_BYTES)     // 50176
#define SMEM_TOTAL    (SMEM_B + STAGES * B_STAGE_BYTES)     // 123904

// fp16 scratch: converted weight matrix + recurrent carry (K-major [nw][c])
__device__ __align__(16) __half g_Wh[CDU_C * CDU_C];
__device__ __align__(16) __half g_carry[CDU_NW * CDU_C];

// ---------------------------------------------------------------------------
// PTX helpers (base-ISA only: no tcgen05 / no 'a'-gated features)
// ---------------------------------------------------------------------------
__device__ __forceinline__ uint32_t elect_one_pred() {
    uint32_t pred;
    asm volatile(
        "{\n\t.reg .pred p;\n\telect.sync _|p, 0xFFFFFFFF;\n\t"
        "selp.b32 %0, 1, 0, p;\n\t}" : "=r"(pred));
    return pred;
}
__device__ __forceinline__ uint32_t smem_to_u32(const void* p) {
    uint32_t a;
    asm("{ .reg .u64 t; cvta.to.shared.u64 t, %1; cvt.u32.u64 %0, t; }" : "=r"(a) : "l"(p));
    return a;
}

#define MBARRIER_INIT(addr, cnt) \
    asm volatile("mbarrier.init.shared.b64 [%0], %1;" :: "r"((uint32_t)(addr)), "r"((uint32_t)(cnt)) : "memory")
#define MBARRIER_EXPECT_TX(addr, bytes) \
    asm volatile("mbarrier.arrive.expect_tx.shared.b64 _, [%0], %1;" :: "r"((uint32_t)(addr)), "r"((uint32_t)(bytes)) : "memory")
#define MBARRIER_ARRIVE(addr) \
    asm volatile("mbarrier.arrive.shared.b64 _, [%0];" :: "r"((uint32_t)(addr)) : "memory")

#define MBARRIER_WAIT_PARITY(mbar_smem_addr, phase_parity) do { \
    uint32_t _mbar = (uint32_t)(mbar_smem_addr); \
    uint32_t _parity = (uint32_t)(phase_parity); \
    uint32_t _done; \
    asm volatile( \
        "{\n\t.reg .pred p;\n\t" \
        "mbarrier.try_wait.parity.acquire.cta.shared::cta.b64 p, [%1], %2;\n\t" \
        "selp.b32 %0, 1, 0, p;\n\t}" \
        : "=r"(_done) : "r"(_mbar), "r"(_parity) : "memory"); \
    if (!_done) { \
        asm volatile( \
            "{\n\t.reg .pred P1;\n\t" \
            "WAIT_LOOP_%=:\n\t" \
            "mbarrier.try_wait.parity.acquire.cta.shared::cta.b64 P1, [%0], %1, 0x989680;\n\t" \
            "@P1 bra.uni WAIT_DONE_%=;\n\t" \
            "bra.uni WAIT_LOOP_%=;\n\t" \
            "WAIT_DONE_%=:\n\t}" \
            :: "r"(_mbar), "r"(_parity) : "memory"); \
    } \
} while (0)

__device__ __forceinline__ void tma_load_2d(uint32_t smem_addr, const void* tmap,
                                            int32_t cx, int32_t cy, uint32_t mbar) {
    asm volatile(
        "cp.async.bulk.tensor.2d.shared::cta.global.tile.mbarrier::complete_tx::bytes "
        "[%0], [%1, {%2, %3}], [%4];"
        :: "r"(smem_addr), "l"(tmap), "r"(cx), "r"(cy), "r"(mbar) : "memory");
}

#define LDSM_X4(r0, r1, r2, r3, addr) \
    asm volatile("ldmatrix.sync.aligned.m8n8.x4.shared.b16 {%0,%1,%2,%3}, [%4];" \
        : "=r"(r0), "=r"(r1), "=r"(r2), "=r"(r3) : "r"(addr))
#define LDSM_X2(r0, r1, addr) \
    asm volatile("ldmatrix.sync.aligned.m8n8.x2.shared.b16 {%0,%1}, [%2];" \
        : "=r"(r0), "=r"(r1) : "r"(addr))

#define MMA_16816(d, a, b0, b1) \
    asm volatile("mma.sync.aligned.m16n8k16.row.col.f32.f16.f16.f32 " \
        "{%0,%1,%2,%3}, {%4,%5,%6,%7}, {%8,%9}, {%0,%1,%2,%3};" \
        : "+f"((d)[0]), "+f"((d)[1]), "+f"((d)[2]), "+f"((d)[3]) \
        : "r"((a)[0]), "r"((a)[1]), "r"((a)[2]), "r"((a)[3]), "r"(b0), "r"(b1))

// ---------------------------------------------------------------------------
// Prep kernels
// ---------------------------------------------------------------------------
__global__ void cdu_wconv_kernel(const float* __restrict__ Wsrc) {
    int i = blockIdx.x * blockDim.x + threadIdx.x;
    if (i < CDU_C * CDU_C)
        g_Wh[i] = __float2half(Wsrc[(size_t)i * 9 + 4]);   // W[o, c, 4, 0]
}

__global__ void cdu_init0_kernel(const float* __restrict__ fea, float* __restrict__ out) {
    int i = blockIdx.x * blockDim.x + threadIdx.x;   // i = c * NW + nw
    if (i < CDU_C * CDU_NW) {
        int c = i / CDU_NW, nw = i % CDU_NW;
        int n = nw / CDU_W, w = nw % CDU_W;
        size_t gi = (size_t)(n * CDU_C + c) * CDU_HW + w;  // h = 0
        float v = fea[gi];
        out[gi] = v;
        g_carry[(size_t)nw * CDU_C + c] = __float2half(v);
    }
}

// ---------------------------------------------------------------------------
// One recurrence step: D = relu(Wm @ carry + b) + x ; out/carry <- D
// Grid (32 m-tiles, 4 n-tiles) = 128 CTAs; 160 threads:
//   warps 0-3: ldmatrix + mma.sync consumers (warp tile m32 x n48)
//   warp  4  : TMA producer
// ---------------------------------------------------------------------------
__global__ void __launch_bounds__(160, 1)
cdu_step_kernel(const __grid_constant__ CUtensorMap mapA,
                const __grid_constant__ CUtensorMap mapB,
                const float* __restrict__ xsl,      // x slice base (already + h*W)
                float* __restrict__ osl,            // out slice base (already + h*W)
                const float* __restrict__ bias)
{
    extern __shared__ __align__(1024) char smem[];
    uint32_t sb = smem_to_u32(smem);
    const int tid = threadIdx.x, wid = tid >> 5, lid = tid & 31;
    const int mt = blockIdx.x, nt = blockIdx.y;

    if (tid == 0) {
        for (int s = 0; s < STAGES; s++) {
            MBARRIER_INIT(sb + SMEM_BAR + s * 16, 1);       // full: 1 tx-arrive
            MBARRIER_INIT(sb + SMEM_BAR + s * 16 + 8, 4);   // empty: 4 consumer warps
        }
    }
    __syncthreads();

    if (wid == 4) {
        // ---- TMA producer ----
        if (elect_one_pred()) {
            int s = 0, j = 0;
            for (int it = 0; it < KITERS; it++) {
                if (j > 0) MBARRIER_WAIT_PARITY(sb + SMEM_BAR + s * 16 + 8, (j - 1) & 1);
                MBARRIER_EXPECT_TX(sb + SMEM_BAR + s * 16, A_STAGE_BYTES + B_STAGE_BYTES);
                tma_load_2d(sb + SMEM_A + s * A_STAGE_BYTES, &mapA,
                            it * KC, mt * M_TILE, sb + SMEM_BAR + s * 16);
                tma_load_2d(sb + SMEM_B + s * B_STAGE_BYTES, &mapB,
                            it * KC, nt * N_TILE, sb + SMEM_BAR + s * 16);
                if (++s == STAGES) { s = 0; ++j; }
            }
        }
        return;
    }

    // ---- consumers: warps 0..3, warp tile m32 x n48 ----
    const int wm = wid & 1;        // m offset = wm*32
    const int wn = wid >> 1;       // n offset = wn*48

    float d[2][6][4];
    #pragma unroll
    for (int fm = 0; fm < 2; fm++)
        #pragma unroll
        for (int fn = 0; fn < 6; fn++)
            #pragma unroll
            for (int q = 0; q < 4; q++) d[fm][fn][q] = 0.f;

    {
        int s = 0, ph = 0;
        for (int it = 0; it < KITERS; it++) {
            MBARRIER_WAIT_PARITY(sb + SMEM_BAR + s * 16, ph);
            const uint32_t aBase = sb + SMEM_A + s * A_STAGE_BYTES;
            const uint32_t bBase = sb + SMEM_B + s * B_STAGE_BYTES;
            #pragma unroll
            for (int kk = 0; kk < KC / 16; kk++) {
                uint32_t a[2][4];
                #pragma unroll
                for (int fm = 0; fm < 2; fm++) {
                    int row = wm * 32 + fm * 16 + (lid & 15);
                    int col = kk * 32 + ((lid >> 4) << 4);
                    uint32_t off = row * 128 + (col ^ ((row & 7) << 4));  // SW128
                    LDSM_X4(a[fm][0], a[fm][1], a[fm][2], a[fm][3], aBase + off);
                }
                #pragma unroll
                for (int fn = 0; fn < 6; fn++) {
                    int row = wn * 48 + fn * 8 + (lid & 7);
                    int col = kk * 32 + (((lid >> 3) & 1) << 4);
                    uint32_t off = row * 128 + (col ^ ((row & 7) << 4));  // SW128
                    uint32_t b0, b1;
                    LDSM_X2(b0, b1, bBase + off);
                    MMA_16816(d[0][fn], a[0], b0, b1);
                    MMA_16816(d[1][fn], a[1], b0, b1);
                }
            }
            if (elect_one_pred()) MBARRIER_ARRIVE(sb + SMEM_BAR + s * 16 + 8);
            if (++s == STAGES) { s = 0; ph ^= 1; }
        }
    }

    // ---- epilogue: D frag rows = out channel c, cols = w (2 consecutive) ----
    const int r = lid >> 2, cq = (lid & 3) * 2;
    #pragma unroll
    for (int fm = 0; fm < 2; fm++) {
        const int c0 = mt * M_TILE + wm * 32 + fm * 16 + r;
        const int c1 = c0 + 8;
        const float bv0 = bias[c0], bv1 = bias[c1];
        const float* xr0 = xsl + (size_t)(nt * CDU_C + c0) * CDU_HW;
        const float* xr1 = xsl + (size_t)(nt * CDU_C + c1) * CDU_HW;
        float* or0 = osl + (size_t)(nt * CDU_C + c0) * CDU_HW;
        float* or1 = osl + (size_t)(nt * CDU_C + c1) * CDU_HW;
        #pragma unroll
        for (int fn = 0; fn < 6; fn++) {
            const int w0 = wn * 48 + fn * 8 + cq;
            float2 xv0 = *reinterpret_cast<const float2*>(xr0 + w0);
            float2 xv1 = *reinterpret_cast<const float2*>(xr1 + w0);
            float2 o0, o1;
            o0.x = fmaxf(d[fm][fn][0] + bv0, 0.f) + xv0.x;
            o0.y = fmaxf(d[fm][fn][1] + bv0, 0.f) + xv0.y;
            o1.x = fmaxf(d[fm][fn][2] + bv1, 0.f) + xv1.x;
            o1.y = fmaxf(d[fm][fn][3] + bv1, 0.f) + xv1.y;
            *reinterpret_cast<float2*>(or0 + w0) = o0;
            *reinterpret_cast<float2*>(or1 + w0) = o1;
            // carry (fp16, K-major [nw][c]) for the next step's B operand
            const size_t nwb = (size_t)(nt * N_TILE + w0);
            g_carry[nwb * CDU_C + c0]       = __float2half(o0.x);
            g_carry[(nwb + 1) * CDU_C + c0] = __float2half(o0.y);
            g_carry[nwb * CDU_C + c1]       = __float2half(o1.x);
            g_carry[(nwb + 1) * CDU_C + c1] = __float2half(o1.y);
        }
    }
}

// ---------------------------------------------------------------------------
// Host
// ---------------------------------------------------------------------------
typedef CUresult (*cdu_encode_fn)(CUtensorMap*, CUtensorMapDataType, cuuint32_t, void*,
                                  const cuuint64_t*, const cuuint64_t*, const cuuint32_t*,
                                  const cuuint32_t*, CUtensorMapInterleave, CUtensorMapSwizzle,
                                  CUtensorMapL2promotion, CUtensorMapFloatOOBfill);

extern "C" void kernel_launch(void* const* d_in, const int* in_sizes, int n_in,
                              void* d_out, int out_size) {
    const float* fea = (const float*)d_in[0];
    const float* Wt  = (const float*)d_in[1];
    const float* b   = (const float*)d_in[2];
    float* out = (float*)d_out;

    void* whp = nullptr;  cudaGetSymbolAddress(&whp, g_Wh);
    void* cp  = nullptr;  cudaGetSymbolAddress(&cp, g_carry);

    cdu_encode_fn enc = nullptr;
    cudaDriverEntryPointQueryResult qr;
    cudaGetDriverEntryPointByVersion("cuTensorMapEncodeTiled", (void**)&enc, 12000,
                                     cudaEnableDefault, &qr);

    CUtensorMap mapA, mapB;
    {
        cuuint64_t dimsA[2]  = {CDU_C, CDU_C};
        cuuint64_t stride[1] = {CDU_C * sizeof(__half)};
        cuuint32_t boxA[2]   = {KC, M_TILE};
        cuuint32_t es[2]     = {1, 1};
        enc(&mapA, CU_TENSOR_MAP_DATA_TYPE_FLOAT16, 2, whp, dimsA, stride, boxA, es,
            CU_TENSOR_MAP_INTERLEAVE_NONE, CU_TENSOR_MAP_SWIZZLE_128B,
            CU_TENSOR_MAP_L2_PROMOTION_L2_128B, CU_TENSOR_MAP_FLOAT_OOB_FILL_NONE);
        cuuint64_t dimsB[2]  = {CDU_C, CDU_NW};
        cuuint32_t boxB[2]   = {KC, N_TILE};
        enc(&mapB, CU_TENSOR_MAP_DATA_TYPE_FLOAT16, 2, cp, dimsB, stride, boxB, es,
            CU_TENSOR_MAP_INTERLEAVE_NONE, CU_TENSOR_MAP_SWIZZLE_128B,
            CU_TENSOR_MAP_L2_PROMOTION_L2_128B, CU_TENSOR_MAP_FLOAT_OOB_FILL_NONE);
    }

    cudaFuncSetAttribute(cdu_step_kernel, cudaFuncAttributeMaxDynamicSharedMemorySize, SMEM_TOTAL);

    cdu_wconv_kernel<<<(CDU_C * CDU_C + 255) / 256, 256>>>(Wt);
    cdu_init0_kernel<<<(CDU_C * CDU_NW + 255) / 256, 256>>>(fea, out);

    dim3 grid(CDU_C / M_TILE, CDU_NW / N_TILE);   // (32, 4)
    // forward scan: h = 1..47
    for (int h = 1; h < CDU_H; h++)
        cdu_step_kernel<<<grid, 160, SMEM_TOTAL>>>(mapA, mapB, fea + h * CDU_W, out + h * CDU_W, b);
    // backward scan: h = 46..0 (x = down[h] staged in out)
    for (int h = CDU_H - 2; h >= 0; h--)
        cdu_step_kernel<<<grid, 160, SMEM_TOTAL>>>(mapA, mapB, out + h * CDU_W, out + h * CDU_W, b);
}